// round 14
// baseline (speedup 1.0000x reference)
#include <cuda_runtime.h>
#include <cstdint>

#define NN 2048
#define TT 16
#define DD 16
#define HH 64
#define NP (NN*NN)          // 4194304 pairs
#define NP2 (NP/2)          // 2097152 pair-pairs (512B each)
#define NBATCH (NP2/16)     // 131072 batches (16 p2 = 32 pairs = 8KB each)
#define CHUNK 4             // batches per atomic grab
#define NCHUNK (NBATCH/CHUNK)
#define FB 148              // fused-epilogue blocks (one per SM, co-resident)

// ---------------- device scratch (static, no allocation) ----------------
__device__ __align__(16) float g_E0[NP];          // 16 MB: exp(leaky(rel.w1+b1)+mask)
__device__ __align__(16) float g_emb[NN*HH];      // LSTM last hidden
__device__ __align__(16) float g_era[NN];         // exp(leaky(emb.w2+b2)+leaky(emb.w3+b3))
__device__ __align__(16) float g_Z[NN];           // column sums (atomic accumulated)
__device__ __align__(16) float g_q[NN];           // (emb[j].w4b) / Z_j
__device__ __align__(16) float g_base[NN];        // b4 + emb[j].w4a
__device__ unsigned int g_cnt = 0;                // rel work-steal counter
__device__ unsigned int g_bar[3] = {0, 0, 0};     // grid barriers (reset by k1)

__device__ __forceinline__ float sigm(float v) {
    v = fminf(fmaxf(v, -30.f), 30.f);
    return __fdividef(1.f, 1.f + __expf(-v));
}
__device__ __forceinline__ float tanhx(float v) {
    v = fminf(fmaxf(v, -30.f), 30.f);
    float e = __expf(-2.f * v);
    return __fdividef(1.f - e, 1.f + e);
}
__device__ __forceinline__ float leaky(float v) { return fmaxf(0.2f * v, v); }

// f32x2 helpers
__device__ __forceinline__ void fma2(unsigned long long& acc,
                                     unsigned long long a, unsigned long long b) {
    asm("fma.rn.f32x2 %0, %1, %2, %0;" : "+l"(acc) : "l"(a), "l"(b));
}
__device__ __forceinline__ unsigned long long pk2(float x, float y) {
    unsigned long long r;
    asm("mov.b64 %0, {%1, %2};" : "=l"(r) : "f"(x), "f"(y));
    return r;
}
__device__ __forceinline__ void upk2(float& x, float& y, unsigned long long v) {
    asm("mov.b64 {%0, %1}, %2;" : "=f"(x), "=f"(y) : "l"(v));
}
__device__ __forceinline__ void lds2x64(unsigned long long& a, unsigned long long& b,
                                        unsigned int addr) {
    asm volatile("ld.shared.v2.b64 {%0, %1}, [%2];" : "=l"(a), "=l"(b) : "r"(addr));
}
__device__ __forceinline__ unsigned int smem_u32(const void* p) {
    unsigned int a;
    asm("{ .reg .u64 t; cvta.to.shared.u64 t, %1; cvt.u32.u64 %0, t; }" : "=r"(a) : "l"(p));
    return a;
}

// grid barrier: all FB blocks co-resident (one per SM)
__device__ __forceinline__ void grid_bar(int idx) {
    __syncthreads();
    if (threadIdx.x == 0) {
        __threadfence();
        atomicAdd(&g_bar[idx], 1u);
        while (*((volatile unsigned int*)&g_bar[idx]) < FB) { }
    }
    __syncthreads();
}

// ---------------- K1: fused LSTM + work-stealing relation stream -------------
#define K1_BLOCKS 148
#define LSTM_BLOCKS 128
#define K1_THREADS 768

// smem float offsets (LSTM blocks only use these)
#define SM_WHH 0          // 64*64*4 floats (layout [(k*64+j)*4 + gate])
#define SM_WIH 16384      // 16*64*4
#define SM_X   20480      // 16 rows * 256
#define SM_H   24576      // 2 * 16 * 64
#define SM_TOT 26624      // floats -> 106496 bytes

// one batch of 16 pair-pairs (32 pairs = 8KB of rel); MLP=16 (R10-proven form)
__device__ __forceinline__ void rel_batch(
    const float4* __restrict__ rel4, const float* __restrict__ mask,
    long base, int lane, float4 w1v, float b1v)
{
    const int myk = lane & 15;
    long p = 2 * base + 2 * myk + (lane >> 4);
    float mk = __ldcs(mask + p);

    float4 v[16];
    const float4* src = rel4 + base * 32 + lane;
    #pragma unroll
    for (int k = 0; k < 16; k++) v[k] = __ldcs(src + k * 32);

    float myS = 0.f;
    #pragma unroll
    for (int k = 0; k < 16; k++) {
        float s = v[k].x * w1v.x + v[k].y * w1v.y
                + v[k].z * w1v.z + v[k].w * w1v.w;
        // width-16 XOR butterfly = allreduce within each 16-lane half
        s += __shfl_xor_sync(0xffffffffu, s, 8, 16);
        s += __shfl_xor_sync(0xffffffffu, s, 4, 16);
        s += __shfl_xor_sync(0xffffffffu, s, 2, 16);
        s += __shfl_xor_sync(0xffffffffu, s, 1, 16);
        if (myk == k) myS = s;    // lane keeps its own pair's sum
    }
    g_E0[p] = __expf(leaky(myS + b1v) + mk);
}

// simple work-steal loop (R10-proven; pipelined grab regressed)
__device__ __forceinline__ void rel_loop(
    const float4* __restrict__ rel4, const float* __restrict__ mask,
    int lane, float4 w1v, float b1v)
{
    for (;;) {
        unsigned int c;
        if (lane == 0) c = atomicAdd(&g_cnt, 1u);
        c = __shfl_sync(0xffffffffu, c, 0);
        if (c >= NCHUNK) break;
        long base0 = (long)c * (CHUNK * 16);
        #pragma unroll
        for (int b = 0; b < CHUNK; b++)
            rel_batch(rel4, mask, base0 + b * 16, lane, w1v, b1v);
    }
}

__global__ __launch_bounds__(K1_THREADS, 1)
void k1_lstm_rel(const float* __restrict__ x, const float* __restrict__ rel,
                 const float* __restrict__ mask,
                 const float* __restrict__ Wih, const float* __restrict__ Whh,
                 const float* __restrict__ bih, const float* __restrict__ bhh,
                 const float* __restrict__ w1, const float* __restrict__ b1p)
{
    extern __shared__ float sm[];
    const int tid = threadIdx.x;
    const int w = tid >> 5;
    const int bx = blockIdx.x;
    const bool lstmB = (bx < LSTM_BLOCKS);
    const int lane = tid & 31;
    const int sub = lane & 15;
    const float4 w1v = *(const float4*)(w1 + sub * 4);
    const float b1v = __ldg(b1p);
    const float4* rel4 = (const float4*)rel;

    // reset epilogue barriers for this replay (read only by the NEXT kernel)
    if (bx == 0 && tid == 0) { g_bar[0] = 0; g_bar[1] = 0; g_bar[2] = 0; }

    if (lstmB && w < 8) {
        // ---------------- LSTM role: 256 threads, 16 rows, f32x2 gates -------
        const int j  = tid & 63;
        const int rg = tid >> 6;
        const int r0 = rg * 4;
        const int row0 = bx * 16;

        float* Whh_P = sm + SM_WHH;
        float* Wih_P = sm + SM_WIH;
        float* x_s   = sm + SM_X;
        float* h_s   = sm + SM_H;

        for (int idx = tid; idx < 16384; idx += 256) {
            int gr = idx >> 6, k = idx & 63;
            int gate = gr >> 6, jj = gr & 63;
            Whh_P[((k << 6) + jj) * 4 + gate] = Whh[idx];
        }
        for (int idx = tid; idx < 4096; idx += 256) {
            int gr = idx >> 4, d = idx & 15;
            int gate = gr >> 6, jj = gr & 63;
            Wih_P[((d << 6) + jj) * 4 + gate] = Wih[idx];
        }
        for (int idx = tid; idx < 16 * TT * DD; idx += 256)
            x_s[idx] = x[(size_t)row0 * TT * DD + idx];
        for (int idx = tid; idx < 2048; idx += 256) h_s[idx] = 0.f;

        const unsigned long long bIF = pk2(bih[j] + bhh[j], bih[64 + j] + bhh[64 + j]);
        const unsigned long long bGO = pk2(bih[128 + j] + bhh[128 + j], bih[192 + j] + bhh[192 + j]);

        const unsigned int wih_a = smem_u32(Wih_P) + (unsigned)j * 16;
        const unsigned int whh_a = smem_u32(Whh_P) + (unsigned)j * 16;

        float c[4] = {0.f, 0.f, 0.f, 0.f};
        asm volatile("bar.sync 1, 256;" ::: "memory");

        int buf = 0;
        for (int t = 0; t < TT; t++) {
            unsigned long long aIF[4], aGO[4];
            #pragma unroll
            for (int q = 0; q < 4; q++) { aIF[q] = bIF; aGO[q] = bGO; }

            const float* xb = x_s + t * DD;
            #pragma unroll
            for (int d = 0; d < DD; d++) {
                unsigned long long wIF, wGO;
                lds2x64(wIF, wGO, wih_a + (unsigned)d * 1024);
                #pragma unroll
                for (int q = 0; q < 4; q++) {
                    float xv = xb[(r0 + q) * 256 + d];
                    unsigned long long x2 = pk2(xv, xv);
                    fma2(aIF[q], wIF, x2);
                    fma2(aGO[q], wGO, x2);
                }
            }
            const float* hb = h_s + buf * 1024;
            #pragma unroll 8
            for (int k = 0; k < HH; k++) {
                unsigned long long wIF, wGO;
                lds2x64(wIF, wGO, whh_a + (unsigned)k * 1024);
                #pragma unroll
                for (int q = 0; q < 4; q++) {
                    float hv = hb[(r0 + q) * 64 + k];
                    unsigned long long h2 = pk2(hv, hv);
                    fma2(aIF[q], wIF, h2);
                    fma2(aGO[q], wGO, h2);
                }
            }
            float* hn = h_s + (buf ^ 1) * 1024;
            #pragma unroll
            for (int q = 0; q < 4; q++) {
                float ai, af, ag, ao;
                upk2(ai, af, aIF[q]);
                upk2(ag, ao, aGO[q]);
                float ig = sigm(ai);
                float fg = sigm(af);
                float gg = tanhx(ag);
                float og = sigm(ao);
                c[q] = fmaf(fg, c[q], ig * gg);
                float hv = og * tanhx(c[q]);
                hn[(r0 + q) * 64 + j] = hv;
                if (t == TT - 1) g_emb[(size_t)(row0 + r0 + q) * 64 + j] = hv;
            }
            asm volatile("bar.sync 1, 256;" ::: "memory");
            buf ^= 1;
        }
        // LSTM done -> join the relation stream
        rel_loop(rel4, mask, lane, w1v, b1v);
    } else {
        // dedicated relation warps start immediately
        rel_loop(rel4, mask, lane, w1v, b1v);
    }
}

// ---------------- K2: fused epilogue (persistent, 148 blocks x 256) ----------
// P0: era (blocks 0-7), zero Z (blocks 8-15), reset g_cnt
// P1: column sums Z_j via spread atomics (1024 warps x 32cols x 128rows)
// P1b: q_j, base_j (blocks 0-7)
// P2: out[i] = leaky(base_i + era_i * E0[i,:].q)  (warp per row)
__global__ __launch_bounds__(256) void k2_fused(
    const float* __restrict__ w2, const float* __restrict__ b2,
    const float* __restrict__ w3, const float* __restrict__ b3,
    const float* __restrict__ w4, const float* __restrict__ b4,
    float* __restrict__ out)
{
    __shared__ float wA[64], wB[64], w4s[128];
    const int tid = threadIdx.x;
    const int bx = blockIdx.x;
    const int wid = tid >> 5, lane = tid & 31;

    // ---- P0 ----
    if (bx == 0 && tid == 0) g_cnt = 0;           // reset rel work-steal counter
    if (bx < 8) {
        if (tid < 64) { wA[tid] = w2[tid]; wB[tid] = w3[tid]; }
        __syncthreads();
        int i = bx * 256 + tid;
        const float4* e4 = (const float4*)(g_emb + (size_t)i * 64);
        float s2 = 0.f, s3 = 0.f;
        #pragma unroll
        for (int k = 0; k < 16; k++) {
            float4 e = e4[k];
            float4 a = ((const float4*)wA)[k];
            float4 b = ((const float4*)wB)[k];
            s2 += e.x*a.x + e.y*a.y + e.z*a.z + e.w*a.w;
            s3 += e.x*b.x + e.y*b.y + e.z*b.z + e.w*b.w;
        }
        s2 += __ldg(b2); s3 += __ldg(b3);
        g_era[i] = __expf(leaky(s2) + leaky(s3));
    } else if (bx < 16) {
        g_Z[(bx - 8) * 256 + tid] = 0.f;
    }
    grid_bar(0);

    // ---- P1: column-sum partials ----
    {
        int u = bx * 8 + wid;                     // 0..1183
        if (u < 1024) {
            int cg = u & 63;                      // column group (32 cols)
            int rc = u >> 6;                      // row chunk (128 rows)
            int j = cg * 32 + lane;
            const float* col = g_E0 + (size_t)(rc * 128) * NN + j;
            const float* er = g_era + rc * 128;
            float acc = 0.f;
            #pragma unroll 8
            for (int r = 0; r < 128; r++)
                acc = fmaf(__ldg(er + r), __ldg(col + (size_t)r * NN), acc);
            atomicAdd(&g_Z[j], acc);
        }
    }
    grid_bar(1);

    // ---- P1b: q and base ----
    if (bx < 8) {
        if (tid < 128) w4s[tid] = w4[tid];
        __syncthreads();
        int j = bx * 256 + tid;
        float iZ = __fdividef(1.f, g_Z[j]);
        const float4* e4 = (const float4*)(g_emb + (size_t)j * 64);
        float da = 0.f, db = 0.f;
        #pragma unroll
        for (int k = 0; k < 16; k++) {
            float4 e = e4[k];
            float4 wa = ((const float4*)w4s)[k];
            float4 wb = ((const float4*)w4s)[16 + k];
            da += e.x*wa.x + e.y*wa.y + e.z*wa.z + e.w*wa.w;
            db += e.x*wb.x + e.y*wb.y + e.z*wb.z + e.w*wb.w;
        }
        g_q[j] = iZ * db;
        g_base[j] = __ldg(b4) + da;
    }
    grid_bar(2);

    // ---- P2: output rows (warp per row, 2 passes) ----
    {
        int u = bx * 8 + wid;                     // 0..1183
        #pragma unroll
        for (int pass = 0; pass < 2; pass++) {
            int i = u + pass * 1184;
            if (i < NN) {
                const float4* e0 = (const float4*)(g_E0 + (size_t)i * NN) + lane;
                const float4* q4 = (const float4*)g_q + lane;
                float acc = 0.f;
                #pragma unroll
                for (int m = 0; m < 16; m++) {
                    float4 v = __ldg(e0 + m * 32);
                    float4 qv = __ldg(q4 + m * 32);
                    acc += v.x*qv.x + v.y*qv.y + v.z*qv.z + v.w*qv.w;
                }
                #pragma unroll
                for (int d = 16; d; d >>= 1)
                    acc += __shfl_xor_sync(0xffffffffu, acc, d);
                if (lane == 0)
                    out[i] = leaky(__ldg(g_base + i) + __ldg(g_era + i) * acc);
            }
        }
    }
}

// ---------------- launch ------------------------------------------------------
extern "C" void kernel_launch(void* const* d_in, const int* in_sizes, int n_in,
                              void* d_out, int out_size)
{
    const float* x    = (const float*)d_in[0];
    const float* rel  = (const float*)d_in[1];
    const float* mask = (const float*)d_in[2];
    const float* Wih  = (const float*)d_in[3];
    const float* Whh  = (const float*)d_in[4];
    const float* bih  = (const float*)d_in[5];
    const float* bhh  = (const float*)d_in[6];
    const float* w1   = (const float*)d_in[7];
    const float* b1   = (const float*)d_in[8];
    const float* w2   = (const float*)d_in[9];
    const float* b2   = (const float*)d_in[10];
    const float* w3   = (const float*)d_in[11];
    const float* b3   = (const float*)d_in[12];
    const float* w4   = (const float*)d_in[13];
    const float* b4   = (const float*)d_in[14];

    cudaFuncSetAttribute(k1_lstm_rel, cudaFuncAttributeMaxDynamicSharedMemorySize,
                         SM_TOT * (int)sizeof(float));

    k1_lstm_rel<<<K1_BLOCKS, K1_THREADS, SM_TOT * sizeof(float)>>>(
        x, rel, mask, Wih, Whh, bih, bhh, w1, b1);
    k2_fused<<<FB, 256>>>(w2, b2, w3, b3, w4, b4, (float*)d_out);
}

// round 15
// speedup vs baseline: 1.0317x; 1.0317x over previous
#include <cuda_runtime.h>
#include <cstdint>

#define NN 2048
#define TT 16
#define DD 16
#define HH 64
#define NP (NN*NN)          // 4194304 pairs
#define NP2 (NP/2)          // 2097152 pair-pairs (512B each)
#define NBATCH (NP2/16)     // 131072 batches (16 p2 = 32 pairs = 8KB each)
#define CHUNK 4             // batches per atomic grab
#define NCHUNK (NBATCH/CHUNK)

// ---------------- device scratch (static, no allocation) ----------------
__device__ __align__(16) float g_E0[NP];          // 16 MB: exp(leaky(rel.w1+b1)+mask)
__device__ __align__(16) float g_emb[NN*HH];      // LSTM last hidden
__device__ __align__(16) float g_era[NN];         // exp(leaky(emb.w2+b2)+leaky(emb.w3+b3))
__device__ __align__(16) float g_zpart[64*NN];    // column-sum partials (64 row-chunks)
__device__ __align__(16) float g_q[NN];           // iZ_j * (emb[j].w4b)
__device__ __align__(16) float g_base[NN];        // b4 + emb[j].w4a
__device__ unsigned int g_cnt = 0;                // rel work-steal counter

__device__ __forceinline__ float sigm(float v) {
    v = fminf(fmaxf(v, -30.f), 30.f);
    return __fdividef(1.f, 1.f + __expf(-v));
}
__device__ __forceinline__ float tanhx(float v) {
    v = fminf(fmaxf(v, -30.f), 30.f);
    float e = __expf(-2.f * v);
    return __fdividef(1.f - e, 1.f + e);
}
__device__ __forceinline__ float leaky(float v) { return fmaxf(0.2f * v, v); }

// f32x2 helpers
__device__ __forceinline__ void fma2(unsigned long long& acc,
                                     unsigned long long a, unsigned long long b) {
    asm("fma.rn.f32x2 %0, %1, %2, %0;" : "+l"(acc) : "l"(a), "l"(b));
}
__device__ __forceinline__ unsigned long long pk2(float x, float y) {
    unsigned long long r;
    asm("mov.b64 %0, {%1, %2};" : "=l"(r) : "f"(x), "f"(y));
    return r;
}
__device__ __forceinline__ void upk2(float& x, float& y, unsigned long long v) {
    asm("mov.b64 {%0, %1}, %2;" : "=f"(x), "=f"(y) : "l"(v));
}
__device__ __forceinline__ void lds2x64(unsigned long long& a, unsigned long long& b,
                                        unsigned int addr) {
    asm volatile("ld.shared.v2.b64 {%0, %1}, [%2];" : "=l"(a), "=l"(b) : "r"(addr));
}
__device__ __forceinline__ unsigned int smem_u32(const void* p) {
    unsigned int a;
    asm("{ .reg .u64 t; cvta.to.shared.u64 t, %1; cvt.u32.u64 %0, t; }" : "=r"(a) : "l"(p));
    return a;
}

// ---------------- K1: fused LSTM + work-stealing relation stream (R10) -------
#define K1_BLOCKS 148
#define LSTM_BLOCKS 128
#define K1_THREADS 768

// smem float offsets (LSTM blocks only use these)
#define SM_WHH 0          // 64*64*4 floats (layout [(k*64+j)*4 + gate])
#define SM_WIH 16384      // 16*64*4
#define SM_X   20480      // 16 rows * 256
#define SM_H   24576      // 2 * 16 * 64
#define SM_TOT 26624      // floats -> 106496 bytes

// one batch of 16 pair-pairs (32 pairs = 8KB of rel); MLP=16
__device__ __forceinline__ void rel_batch(
    const float4* __restrict__ rel4, const float* __restrict__ mask,
    long base, int lane, float4 w1v, float b1v)
{
    const int myk = lane & 15;
    long p = 2 * base + 2 * myk + (lane >> 4);
    float mk = __ldcs(mask + p);

    float4 v[16];
    const float4* src = rel4 + base * 32 + lane;
    #pragma unroll
    for (int k = 0; k < 16; k++) v[k] = __ldcs(src + k * 32);

    float myS = 0.f;
    #pragma unroll
    for (int k = 0; k < 16; k++) {
        float s = v[k].x * w1v.x + v[k].y * w1v.y
                + v[k].z * w1v.z + v[k].w * w1v.w;
        // width-16 XOR butterfly = allreduce within each 16-lane half
        s += __shfl_xor_sync(0xffffffffu, s, 8, 16);
        s += __shfl_xor_sync(0xffffffffu, s, 4, 16);
        s += __shfl_xor_sync(0xffffffffu, s, 2, 16);
        s += __shfl_xor_sync(0xffffffffu, s, 1, 16);
        if (myk == k) myS = s;    // lane keeps its own pair's sum
    }
    g_E0[p] = __expf(leaky(myS + b1v) + mk);
}

// simple work-steal loop (R10-proven)
__device__ __forceinline__ void rel_loop(
    const float4* __restrict__ rel4, const float* __restrict__ mask,
    int lane, float4 w1v, float b1v)
{
    for (;;) {
        unsigned int c;
        if (lane == 0) c = atomicAdd(&g_cnt, 1u);
        c = __shfl_sync(0xffffffffu, c, 0);
        if (c >= NCHUNK) break;
        long base0 = (long)c * (CHUNK * 16);
        #pragma unroll
        for (int b = 0; b < CHUNK; b++)
            rel_batch(rel4, mask, base0 + b * 16, lane, w1v, b1v);
    }
}

__global__ __launch_bounds__(K1_THREADS, 1)
void k1_lstm_rel(const float* __restrict__ x, const float* __restrict__ rel,
                 const float* __restrict__ mask,
                 const float* __restrict__ Wih, const float* __restrict__ Whh,
                 const float* __restrict__ bih, const float* __restrict__ bhh,
                 const float* __restrict__ w1, const float* __restrict__ b1p)
{
    extern __shared__ float sm[];
    const int tid = threadIdx.x;
    const int w = tid >> 5;
    const int bx = blockIdx.x;
    const bool lstmB = (bx < LSTM_BLOCKS);
    const int lane = tid & 31;
    const int sub = lane & 15;
    const float4 w1v = *(const float4*)(w1 + sub * 4);
    const float b1v = __ldg(b1p);
    const float4* rel4 = (const float4*)rel;

    if (lstmB && w < 8) {
        // ---------------- LSTM role: 256 threads, 16 rows, f32x2 gates -------
        const int j  = tid & 63;
        const int rg = tid >> 6;
        const int r0 = rg * 4;
        const int row0 = bx * 16;

        float* Whh_P = sm + SM_WHH;
        float* Wih_P = sm + SM_WIH;
        float* x_s   = sm + SM_X;
        float* h_s   = sm + SM_H;

        for (int idx = tid; idx < 16384; idx += 256) {
            int gr = idx >> 6, k = idx & 63;
            int gate = gr >> 6, jj = gr & 63;
            Whh_P[((k << 6) + jj) * 4 + gate] = Whh[idx];
        }
        for (int idx = tid; idx < 4096; idx += 256) {
            int gr = idx >> 4, d = idx & 15;
            int gate = gr >> 6, jj = gr & 63;
            Wih_P[((d << 6) + jj) * 4 + gate] = Wih[idx];
        }
        for (int idx = tid; idx < 16 * TT * DD; idx += 256)
            x_s[idx] = x[(size_t)row0 * TT * DD + idx];
        for (int idx = tid; idx < 2048; idx += 256) h_s[idx] = 0.f;

        const unsigned long long bIF = pk2(bih[j] + bhh[j], bih[64 + j] + bhh[64 + j]);
        const unsigned long long bGO = pk2(bih[128 + j] + bhh[128 + j], bih[192 + j] + bhh[192 + j]);

        const unsigned int wih_a = smem_u32(Wih_P) + (unsigned)j * 16;
        const unsigned int whh_a = smem_u32(Whh_P) + (unsigned)j * 16;

        float c[4] = {0.f, 0.f, 0.f, 0.f};
        asm volatile("bar.sync 1, 256;" ::: "memory");

        int buf = 0;
        for (int t = 0; t < TT; t++) {
            unsigned long long aIF[4], aGO[4];
            #pragma unroll
            for (int q = 0; q < 4; q++) { aIF[q] = bIF; aGO[q] = bGO; }

            const float* xb = x_s + t * DD;
            #pragma unroll
            for (int d = 0; d < DD; d++) {
                unsigned long long wIF, wGO;
                lds2x64(wIF, wGO, wih_a + (unsigned)d * 1024);
                #pragma unroll
                for (int q = 0; q < 4; q++) {
                    float xv = xb[(r0 + q) * 256 + d];
                    unsigned long long x2 = pk2(xv, xv);
                    fma2(aIF[q], wIF, x2);
                    fma2(aGO[q], wGO, x2);
                }
            }
            const float* hb = h_s + buf * 1024;
            #pragma unroll 8
            for (int k = 0; k < HH; k++) {
                unsigned long long wIF, wGO;
                lds2x64(wIF, wGO, whh_a + (unsigned)k * 1024);
                #pragma unroll
                for (int q = 0; q < 4; q++) {
                    float hv = hb[(r0 + q) * 64 + k];
                    unsigned long long h2 = pk2(hv, hv);
                    fma2(aIF[q], wIF, h2);
                    fma2(aGO[q], wGO, h2);
                }
            }
            float* hn = h_s + (buf ^ 1) * 1024;
            #pragma unroll
            for (int q = 0; q < 4; q++) {
                float ai, af, ag, ao;
                upk2(ai, af, aIF[q]);
                upk2(ag, ao, aGO[q]);
                float ig = sigm(ai);
                float fg = sigm(af);
                float gg = tanhx(ag);
                float og = sigm(ao);
                c[q] = fmaf(fg, c[q], ig * gg);
                float hv = og * tanhx(c[q]);
                hn[(r0 + q) * 64 + j] = hv;
                if (t == TT - 1) g_emb[(size_t)(row0 + r0 + q) * 64 + j] = hv;
            }
            asm volatile("bar.sync 1, 256;" ::: "memory");
            buf ^= 1;
        }
        // LSTM done -> join the relation stream
        rel_loop(rel4, mask, lane, w1v, b1v);
    } else {
        // dedicated relation warps start immediately
        rel_loop(rel4, mask, lane, w1v, b1v);
    }
}

// ---------------- K2b: fused era + column-sum partials -----------------------
// grid (NN/256=8, 64): bx = j-block of 256, by = row chunk of 32
__global__ __launch_bounds__(256) void k2b_colsum(
    const float* __restrict__ w2, const float* __restrict__ b2,
    const float* __restrict__ w3, const float* __restrict__ b3)
{
    __shared__ float w2s[64], w3s[64], era_s[32];
    int tid = threadIdx.x;
    if (tid < 64) { w2s[tid] = w2[tid]; w3s[tid] = w3[tid]; }
    __syncthreads();
    int i0 = blockIdx.y * 32;
    if (tid < 32) {
        const float4* e4 = (const float4*)(g_emb + (size_t)(i0 + tid) * 64);
        float s2 = 0.f, s3 = 0.f;
        #pragma unroll
        for (int k = 0; k < 16; k++) {
            float4 e = e4[k];
            float4 a = ((const float4*)w2s)[k];
            float4 b = ((const float4*)w3s)[k];
            s2 += e.x*a.x + e.y*a.y + e.z*a.z + e.w*a.w;
            s3 += e.x*b.x + e.y*b.y + e.z*b.z + e.w*b.w;
        }
        s2 += __ldg(b2); s3 += __ldg(b3);
        float era = __expf(leaky(s2) + leaky(s3));
        era_s[tid] = era;
        if (blockIdx.x == 0) g_era[i0 + tid] = era;
    }
    __syncthreads();
    int j = blockIdx.x * 256 + tid;
    float acc = 0.f;
    #pragma unroll 8
    for (int r = 0; r < 32; r++)
        acc = fmaf(era_s[r], g_E0[(size_t)(i0 + r) * NN + j], acc);
    g_zpart[blockIdx.y * NN + j] = acc;
}

// ---------------- K3q: q[j] = iZ_j*(emb[j].w4b); base[j] = b4 + emb[j].w4a ---
__global__ __launch_bounds__(128) void k3_q(const float* __restrict__ w4,
                                            const float* __restrict__ b4)
{
    __shared__ float w4s[128];
    int tid = threadIdx.x;
    w4s[tid] = w4[tid];
    __syncthreads();
    int j = blockIdx.x * 128 + tid;
    float s = 0.f;
    #pragma unroll
    for (int c = 0; c < 64; c++) s += g_zpart[c * NN + j];
    float iZ = __fdividef(1.f, s);
    const float4* e4 = (const float4*)(g_emb + (size_t)j * 64);
    float da = 0.f, db = 0.f;
    #pragma unroll
    for (int k = 0; k < 16; k++) {
        float4 e = e4[k];
        float4 wa = ((const float4*)w4s)[k];
        float4 wb = ((const float4*)w4s)[16 + k];
        da += e.x*wa.x + e.y*wa.y + e.z*wa.z + e.w*wa.w;
        db += e.x*wb.x + e.y*wb.y + e.z*wb.z + e.w*wb.w;
    }
    g_q[j] = iZ * db;
    g_base[j] = __ldg(b4) + da;
}

// ---------------- K4f: out[i] = leaky(base_i + era_i * sum_j E0[i,j]*q_j) ----
// grid 512 blocks x 256 threads: 4 rows/block, 2 warps per row, q in smem
__global__ __launch_bounds__(256) void k4_final(float* __restrict__ out)
{
    __shared__ __align__(16) float q_s[NN];
    __shared__ float part[8];
    int tid = threadIdx.x;
    int wid = tid >> 5, lane = tid & 31;
    if (blockIdx.x == 0 && tid == 0) g_cnt = 0;   // reset work-steal counter

    #pragma unroll
    for (int u = 0; u < 2; u++)
        ((float4*)q_s)[tid + u * 256] = ((const float4*)g_q)[tid + u * 256];
    __syncthreads();

    int i = blockIdx.x * 4 + (wid >> 1);          // 4 rows per block
    int half = wid & 1;                            // half-row per warp
    const float4* e0 = (const float4*)(g_E0 + (size_t)i * NN) + half * 256 + lane;
    const float4* q4 = (const float4*)q_s + half * 256 + lane;
    float acc = 0.f;
    #pragma unroll
    for (int m = 0; m < 8; m++) {
        float4 v = __ldg(e0 + m * 32);
        float4 qv = q4[m * 32];
        acc += v.x*qv.x + v.y*qv.y + v.z*qv.z + v.w*qv.w;
    }
    #pragma unroll
    for (int d = 16; d; d >>= 1)
        acc += __shfl_xor_sync(0xffffffffu, acc, d);
    if (lane == 0) part[wid] = acc;
    __syncthreads();
    if (tid < 4) {
        int ii = blockIdx.x * 4 + tid;
        float s = part[2 * tid] + part[2 * tid + 1];
        out[ii] = leaky(g_base[ii] + __ldg(g_era + ii) * s);
    }
}

// ---------------- launch ------------------------------------------------------
extern "C" void kernel_launch(void* const* d_in, const int* in_sizes, int n_in,
                              void* d_out, int out_size)
{
    const float* x    = (const float*)d_in[0];
    const float* rel  = (const float*)d_in[1];
    const float* mask = (const float*)d_in[2];
    const float* Wih  = (const float*)d_in[3];
    const float* Whh  = (const float*)d_in[4];
    const float* bih  = (const float*)d_in[5];
    const float* bhh  = (const float*)d_in[6];
    const float* w1   = (const float*)d_in[7];
    const float* b1   = (const float*)d_in[8];
    const float* w2   = (const float*)d_in[9];
    const float* b2   = (const float*)d_in[10];
    const float* w3   = (const float*)d_in[11];
    const float* b3   = (const float*)d_in[12];
    const float* w4   = (const float*)d_in[13];
    const float* b4   = (const float*)d_in[14];

    cudaFuncSetAttribute(k1_lstm_rel, cudaFuncAttributeMaxDynamicSharedMemorySize,
                         SM_TOT * (int)sizeof(float));

    k1_lstm_rel<<<K1_BLOCKS, K1_THREADS, SM_TOT * sizeof(float)>>>(
        x, rel, mask, Wih, Whh, bih, bhh, w1, b1);
    k2b_colsum<<<dim3(NN / 256, 64), 256>>>(w2, b2, w3, b3);
    k3_q<<<NN / 128, 128>>>(w4, b4);
    k4_final<<<NN / 4, 256>>>((float*)d_out);
}

// round 16
// speedup vs baseline: 1.0557x; 1.0233x over previous
#include <cuda_runtime.h>
#include <cuda_fp16.h>
#include <cstdint>

#define NN 2048
#define TT 16
#define DD 16
#define HH 64
#define NP (NN*NN)          // 4194304 pairs
#define NP2 (NP/2)          // 2097152 pair-pairs (512B each)
#define NBATCH (NP2/16)     // 131072 batches (16 p2 = 32 pairs = 8KB each)
#define CHUNK 4             // batches per atomic grab
#define NCHUNK (NBATCH/CHUNK)

// ---------------- device scratch (static, no allocation) ----------------
__device__ __align__(16) __half g_E0[NP];         // 8 MB: exp(leaky(rel.w1+b1)+mask), fp16
__device__ __align__(16) float g_emb[NN*HH];      // LSTM last hidden
__device__ __align__(16) float g_era[NN];         // exp(leaky(emb.w2+b2)+leaky(emb.w3+b3))
__device__ __align__(16) float g_zpart[32*NN];    // column-sum partials (32 row-chunks)
__device__ __align__(16) float g_q[NN];           // iZ_j * (emb[j].w4b)
__device__ __align__(16) float g_base[NN];        // b4 + emb[j].w4a
__device__ unsigned int g_cnt = 0;                // rel work-steal counter

__device__ __forceinline__ float sigm(float v) {
    v = fminf(fmaxf(v, -30.f), 30.f);
    return __fdividef(1.f, 1.f + __expf(-v));
}
__device__ __forceinline__ float tanhx(float v) {
    v = fminf(fmaxf(v, -30.f), 30.f);
    float e = __expf(-2.f * v);
    return __fdividef(1.f - e, 1.f + e);
}
__device__ __forceinline__ float leaky(float v) { return fmaxf(0.2f * v, v); }

// f32x2 helpers
__device__ __forceinline__ void fma2(unsigned long long& acc,
                                     unsigned long long a, unsigned long long b) {
    asm("fma.rn.f32x2 %0, %1, %2, %0;" : "+l"(acc) : "l"(a), "l"(b));
}
__device__ __forceinline__ unsigned long long pk2(float x, float y) {
    unsigned long long r;
    asm("mov.b64 %0, {%1, %2};" : "=l"(r) : "f"(x), "f"(y));
    return r;
}
__device__ __forceinline__ void upk2(float& x, float& y, unsigned long long v) {
    asm("mov.b64 {%0, %1}, %2;" : "=f"(x), "=f"(y) : "l"(v));
}
__device__ __forceinline__ void lds2x64(unsigned long long& a, unsigned long long& b,
                                        unsigned int addr) {
    asm volatile("ld.shared.v2.b64 {%0, %1}, [%2];" : "=l"(a), "=l"(b) : "r"(addr));
}
__device__ __forceinline__ unsigned int smem_u32(const void* p) {
    unsigned int a;
    asm("{ .reg .u64 t; cvta.to.shared.u64 t, %1; cvt.u32.u64 %0, t; }" : "=r"(a) : "l"(p));
    return a;
}

// ---------------- K1: fused LSTM + work-stealing relation stream (R10) -------
#define K1_BLOCKS 148
#define LSTM_BLOCKS 128
#define K1_THREADS 768

// smem float offsets (LSTM blocks only use these)
#define SM_WHH 0          // 64*64*4 floats (layout [(k*64+j)*4 + gate])
#define SM_WIH 16384      // 16*64*4
#define SM_X   20480      // 16 rows * 256
#define SM_H   24576      // 2 * 16 * 64
#define SM_TOT 26624      // floats -> 106496 bytes

// one batch of 16 pair-pairs (32 pairs = 8KB of rel); MLP=16
__device__ __forceinline__ void rel_batch(
    const float4* __restrict__ rel4, const float* __restrict__ mask,
    long base, int lane, float4 w1v, float b1v)
{
    const int myk = lane & 15;
    long p = 2 * base + 2 * myk + (lane >> 4);
    float mk = __ldcs(mask + p);

    float4 v[16];
    const float4* src = rel4 + base * 32 + lane;
    #pragma unroll
    for (int k = 0; k < 16; k++) v[k] = __ldcs(src + k * 32);

    float myS = 0.f;
    #pragma unroll
    for (int k = 0; k < 16; k++) {
        float s = v[k].x * w1v.x + v[k].y * w1v.y
                + v[k].z * w1v.z + v[k].w * w1v.w;
        // width-16 XOR butterfly = allreduce within each 16-lane half
        s += __shfl_xor_sync(0xffffffffu, s, 8, 16);
        s += __shfl_xor_sync(0xffffffffu, s, 4, 16);
        s += __shfl_xor_sync(0xffffffffu, s, 2, 16);
        s += __shfl_xor_sync(0xffffffffu, s, 1, 16);
        if (myk == k) myS = s;    // lane keeps its own pair's sum
    }
    g_E0[p] = __float2half_rn(__expf(leaky(myS + b1v) + mk));
}

// simple work-steal loop (R10-proven)
__device__ __forceinline__ void rel_loop(
    const float4* __restrict__ rel4, const float* __restrict__ mask,
    int lane, float4 w1v, float b1v)
{
    for (;;) {
        unsigned int c;
        if (lane == 0) c = atomicAdd(&g_cnt, 1u);
        c = __shfl_sync(0xffffffffu, c, 0);
        if (c >= NCHUNK) break;
        long base0 = (long)c * (CHUNK * 16);
        #pragma unroll
        for (int b = 0; b < CHUNK; b++)
            rel_batch(rel4, mask, base0 + b * 16, lane, w1v, b1v);
    }
}

__global__ __launch_bounds__(K1_THREADS, 1)
void k1_lstm_rel(const float* __restrict__ x, const float* __restrict__ rel,
                 const float* __restrict__ mask,
                 const float* __restrict__ Wih, const float* __restrict__ Whh,
                 const float* __restrict__ bih, const float* __restrict__ bhh,
                 const float* __restrict__ w1, const float* __restrict__ b1p)
{
    extern __shared__ float sm[];
    const int tid = threadIdx.x;
    const int w = tid >> 5;
    const int bx = blockIdx.x;
    const bool lstmB = (bx < LSTM_BLOCKS);
    const int lane = tid & 31;
    const int sub = lane & 15;
    const float4 w1v = *(const float4*)(w1 + sub * 4);
    const float b1v = __ldg(b1p);
    const float4* rel4 = (const float4*)rel;

    if (lstmB && w < 8) {
        // ---------------- LSTM role: 256 threads, 16 rows, f32x2 gates -------
        const int j  = tid & 63;
        const int rg = tid >> 6;
        const int r0 = rg * 4;
        const int row0 = bx * 16;

        float* Whh_P = sm + SM_WHH;
        float* Wih_P = sm + SM_WIH;
        float* x_s   = sm + SM_X;
        float* h_s   = sm + SM_H;

        for (int idx = tid; idx < 16384; idx += 256) {
            int gr = idx >> 6, k = idx & 63;
            int gate = gr >> 6, jj = gr & 63;
            Whh_P[((k << 6) + jj) * 4 + gate] = Whh[idx];
        }
        for (int idx = tid; idx < 4096; idx += 256) {
            int gr = idx >> 4, d = idx & 15;
            int gate = gr >> 6, jj = gr & 63;
            Wih_P[((d << 6) + jj) * 4 + gate] = Wih[idx];
        }
        for (int idx = tid; idx < 16 * TT * DD; idx += 256)
            x_s[idx] = x[(size_t)row0 * TT * DD + idx];
        for (int idx = tid; idx < 2048; idx += 256) h_s[idx] = 0.f;

        const unsigned long long bIF = pk2(bih[j] + bhh[j], bih[64 + j] + bhh[64 + j]);
        const unsigned long long bGO = pk2(bih[128 + j] + bhh[128 + j], bih[192 + j] + bhh[192 + j]);

        const unsigned int wih_a = smem_u32(Wih_P) + (unsigned)j * 16;
        const unsigned int whh_a = smem_u32(Whh_P) + (unsigned)j * 16;

        float c[4] = {0.f, 0.f, 0.f, 0.f};
        asm volatile("bar.sync 1, 256;" ::: "memory");

        int buf = 0;
        for (int t = 0; t < TT; t++) {
            unsigned long long aIF[4], aGO[4];
            #pragma unroll
            for (int q = 0; q < 4; q++) { aIF[q] = bIF; aGO[q] = bGO; }

            const float* xb = x_s + t * DD;
            #pragma unroll
            for (int d = 0; d < DD; d++) {
                unsigned long long wIF, wGO;
                lds2x64(wIF, wGO, wih_a + (unsigned)d * 1024);
                #pragma unroll
                for (int q = 0; q < 4; q++) {
                    float xv = xb[(r0 + q) * 256 + d];
                    unsigned long long x2 = pk2(xv, xv);
                    fma2(aIF[q], wIF, x2);
                    fma2(aGO[q], wGO, x2);
                }
            }
            const float* hb = h_s + buf * 1024;
            #pragma unroll 8
            for (int k = 0; k < HH; k++) {
                unsigned long long wIF, wGO;
                lds2x64(wIF, wGO, whh_a + (unsigned)k * 1024);
                #pragma unroll
                for (int q = 0; q < 4; q++) {
                    float hv = hb[(r0 + q) * 64 + k];
                    unsigned long long h2 = pk2(hv, hv);
                    fma2(aIF[q], wIF, h2);
                    fma2(aGO[q], wGO, h2);
                }
            }
            float* hn = h_s + (buf ^ 1) * 1024;
            #pragma unroll
            for (int q = 0; q < 4; q++) {
                float ai, af, ag, ao;
                upk2(ai, af, aIF[q]);
                upk2(ag, ao, aGO[q]);
                float ig = sigm(ai);
                float fg = sigm(af);
                float gg = tanhx(ag);
                float og = sigm(ao);
                c[q] = fmaf(fg, c[q], ig * gg);
                float hv = og * tanhx(c[q]);
                hn[(r0 + q) * 64 + j] = hv;
                if (t == TT - 1) g_emb[(size_t)(row0 + r0 + q) * 64 + j] = hv;
            }
            asm volatile("bar.sync 1, 256;" ::: "memory");
            buf ^= 1;
        }
        // LSTM done -> join the relation stream
        rel_loop(rel4, mask, lane, w1v, b1v);
    } else {
        // dedicated relation warps start immediately
        rel_loop(rel4, mask, lane, w1v, b1v);
    }
}

// ---------------- K2b: fused era + column-sum partials (R10 shape) -----------
// grid (NN/256=8, 32): bx = j-block of 256, by = row chunk of 64
__global__ __launch_bounds__(256) void k2b_colsum(
    const float* __restrict__ w2, const float* __restrict__ b2,
    const float* __restrict__ w3, const float* __restrict__ b3)
{
    __shared__ float w2s[64], w3s[64], era_s[64];
    int tid = threadIdx.x;
    if (tid < 64) { w2s[tid] = w2[tid]; w3s[tid] = w3[tid]; }
    __syncthreads();
    int i0 = blockIdx.y * 64;
    if (tid < 64) {
        const float4* e4 = (const float4*)(g_emb + (size_t)(i0 + tid) * 64);
        float s2 = 0.f, s3 = 0.f;
        #pragma unroll
        for (int k = 0; k < 16; k++) {
            float4 e = e4[k];
            float4 a = ((const float4*)w2s)[k];
            float4 b = ((const float4*)w3s)[k];
            s2 += e.x*a.x + e.y*a.y + e.z*a.z + e.w*a.w;
            s3 += e.x*b.x + e.y*b.y + e.z*b.z + e.w*b.w;
        }
        s2 += __ldg(b2); s3 += __ldg(b3);
        float era = __expf(leaky(s2) + leaky(s3));
        era_s[tid] = era;
        if (blockIdx.x == 0) g_era[i0 + tid] = era;
    }
    __syncthreads();
    int j = blockIdx.x * 256 + tid;
    float acc = 0.f;
    #pragma unroll 8
    for (int r = 0; r < 64; r++)
        acc = fmaf(era_s[r], __half2float(g_E0[(size_t)(i0 + r) * NN + j]), acc);
    g_zpart[blockIdx.y * NN + j] = acc;
}

// ---------------- K3q: q[j] = iZ_j*(emb[j].w4b); base[j] = b4 + emb[j].w4a ---
__global__ __launch_bounds__(128) void k3_q(const float* __restrict__ w4,
                                            const float* __restrict__ b4)
{
    __shared__ float w4s[128];
    int tid = threadIdx.x;
    w4s[tid] = w4[tid];
    __syncthreads();
    int j = blockIdx.x * 128 + tid;
    float s = 0.f;
    #pragma unroll
    for (int c = 0; c < 32; c++) s += g_zpart[c * NN + j];
    float iZ = __fdividef(1.f, s);
    const float4* e4 = (const float4*)(g_emb + (size_t)j * 64);
    float da = 0.f, db = 0.f;
    #pragma unroll
    for (int k = 0; k < 16; k++) {
        float4 e = e4[k];
        float4 wa = ((const float4*)w4s)[k];
        float4 wb = ((const float4*)w4s)[16 + k];
        da += e.x*wa.x + e.y*wa.y + e.z*wa.z + e.w*wa.w;
        db += e.x*wb.x + e.y*wb.y + e.z*wb.z + e.w*wb.w;
    }
    g_q[j] = iZ * db;
    g_base[j] = __ldg(b4) + da;
}

// ---------------- K4f: out[i] = leaky(base_i + era_i * sum_j E0[i,j]*q_j) ----
// grid 512 blocks x 256 threads: 4 rows/block, 2 warps per row, q in smem
// E0 row read as uint4 (8 halves / 16B per load)
__global__ __launch_bounds__(256) void k4_final(float* __restrict__ out)
{
    __shared__ __align__(16) float q_s[NN];
    __shared__ float part[8];
    int tid = threadIdx.x;
    int wid = tid >> 5, lane = tid & 31;
    if (blockIdx.x == 0 && tid == 0) g_cnt = 0;   // reset work-steal counter

    #pragma unroll
    for (int u = 0; u < 2; u++)
        ((float4*)q_s)[tid + u * 256] = ((const float4*)g_q)[tid + u * 256];
    __syncthreads();

    int i = blockIdx.x * 4 + (wid >> 1);          // 4 rows per block
    int half = wid & 1;                            // half-row (1024 cols) per warp
    const uint4* e0 = (const uint4*)(g_E0 + (size_t)i * NN) + half * 128 + lane;
    const float4* q4 = (const float4*)q_s;
    float acc = 0.f;
    #pragma unroll
    for (int m = 0; m < 4; m++) {
        int idx = half * 128 + m * 32 + lane;      // uint4 index within row
        uint4 v = __ldg(e0 + m * 32);
        float2 f0 = __half22float2(*(const __half2*)&v.x);
        float2 f1 = __half22float2(*(((const __half2*)&v.x) + 1));
        float2 f2 = __half22float2(*(const __half2*)&v.z);
        float2 f3 = __half22float2(*(((const __half2*)&v.z) + 1));
        float4 qa = q4[idx * 2];
        float4 qb = q4[idx * 2 + 1];
        acc += f0.x*qa.x + f0.y*qa.y + f1.x*qa.z + f1.y*qa.w;
        acc += f2.x*qb.x + f2.y*qb.y + f3.x*qb.z + f3.y*qb.w;
    }
    #pragma unroll
    for (int d = 16; d; d >>= 1)
        acc += __shfl_xor_sync(0xffffffffu, acc, d);
    if (lane == 0) part[wid] = acc;
    __syncthreads();
    if (tid < 4) {
        int ii = blockIdx.x * 4 + tid;
        float s = part[2 * tid] + part[2 * tid + 1];
        out[ii] = leaky(g_base[ii] + __ldg(g_era + ii) * s);
    }
}

// ---------------- launch ------------------------------------------------------
extern "C" void kernel_launch(void* const* d_in, const int* in_sizes, int n_in,
                              void* d_out, int out_size)
{
    const float* x    = (const float*)d_in[0];
    const float* rel  = (const float*)d_in[1];
    const float* mask = (const float*)d_in[2];
    const float* Wih  = (const float*)d_in[3];
    const float* Whh  = (const float*)d_in[4];
    const float* bih  = (const float*)d_in[5];
    const float* bhh  = (const float*)d_in[6];
    const float* w1   = (const float*)d_in[7];
    const float* b1   = (const float*)d_in[8];
    const float* w2   = (const float*)d_in[9];
    const float* b2   = (const float*)d_in[10];
    const float* w3   = (const float*)d_in[11];
    const float* b3   = (const float*)d_in[12];
    const float* w4   = (const float*)d_in[13];
    const float* b4   = (const float*)d_in[14];

    cudaFuncSetAttribute(k1_lstm_rel, cudaFuncAttributeMaxDynamicSharedMemorySize,
                         SM_TOT * (int)sizeof(float));

    k1_lstm_rel<<<K1_BLOCKS, K1_THREADS, SM_TOT * sizeof(float)>>>(
        x, rel, mask, Wih, Whh, bih, bhh, w1, b1);
    k2b_colsum<<<dim3(NN / 256, 32), 256>>>(w2, b2, w3, b3);
    k3_q<<<NN / 128, 128>>>(w4, b4);
    k4_final<<<NN / 4, 256>>>((float*)d_out);
}